// round 1
// baseline (speedup 1.0000x reference)
#include <cuda_runtime.h>
#include <math_constants.h>
#include <cstdint>

#define B_ 32
#define C_ 273
#define T_ 4096
#define O_ 270
#define D_ 288

// Device scratch (allocation-free rule: __device__ globals)
__device__ float g_emb[B_ * C_ * D_];   // [B][C][288]  ~10 MB
__device__ float g_w[B_ * O_ * C_];     // [B][O][C]    ~9.4 MB

// ---------------------------------------------------------------------------
// Kernel 1: Fourier embedding. One block per (b,c), 144 threads.
// emb[d]      = cos(loc[d])   d in [0,144)
// emb[144+d]  = sin(loc[d])
// loc[fx*12+fy] = (x+0.1)*p[fx] + (y+0.1)*p[fy],  p[f] = 2*pi*f/1.2
// ---------------------------------------------------------------------------
__global__ void emb_kernel(const float* __restrict__ pos) {
    int bc = blockIdx.x;              // 0..B*C-1
    int i = threadIdx.x;              // 0..143
    float px = pos[bc * 2 + 0] + 0.1f;
    float py = pos[bc * 2 + 1] + 0.1f;
    const float sc = 6.283185307179586f / 1.2f;
    int fx = i / 12;
    int fy = i - fx * 12;
    float loc = px * (sc * (float)fx) + py * (sc * (float)fy);
    float s, c;
    sincosf(loc, &s, &c);
    g_emb[bc * D_ + i] = c;
    g_emb[bc * D_ + 144 + i] = s;
}

// ---------------------------------------------------------------------------
// Kernel 2: scores[b,o,c] = emb[b,c,:] . heads[o,:], then softmax over c.
// One block per (b, 32-o-tile). 256 threads.
// smem: sH[32][292] heads tile, sE[16][292] emb chunk, sS[32][280] scores.
// ---------------------------------------------------------------------------
#define K2_OT 32
#define K2_CH 16
#define K2_SH 292   // 288 + 4 pad (float4-aligned, reduces bank conflicts)
#define K2_SS 280

__global__ void __launch_bounds__(256) scores_kernel(
        const float* __restrict__ heads,
        const unsigned char* __restrict__ mask) {
    extern __shared__ float sm2[];
    float* sH = sm2;                      // [32][K2_SH]
    float* sE = sm2 + K2_OT * K2_SH;      // [16][K2_SH]
    float* sS = sm2 + (K2_OT + K2_CH) * K2_SH;  // [32][K2_SS]

    int b = blockIdx.y;
    int o0 = blockIdx.x * K2_OT;
    int tid = threadIdx.x;

    // Load heads tile [32][288] (zero-pad beyond O_)
    for (int idx = tid; idx < K2_OT * D_; idx += 256) {
        int o = idx / D_, d = idx - o * D_;
        int og = o0 + o;
        sH[o * K2_SH + d] = (og < O_) ? heads[og * D_ + d] : 0.f;
    }

    int o_l = tid & 31;        // which o row this thread computes
    int cp = tid >> 5;         // c-pair group (0..7)
    int c_l0 = cp * 2, c_l1 = cp * 2 + 1;

    for (int c0 = 0; c0 < C_; c0 += K2_CH) {
        __syncthreads();
        // Load emb chunk [16][288]
        for (int idx = tid; idx < K2_CH * D_; idx += 256) {
            int cl = idx / D_, d = idx - cl * D_;
            int cg = c0 + cl;
            sE[cl * K2_SH + d] = (cg < C_) ? g_emb[((size_t)b * C_ + cg) * D_ + d] : 0.f;
        }
        __syncthreads();

        float a0 = 0.f, a1 = 0.f;
        const float4* h4 = (const float4*)(sH + o_l * K2_SH);
        const float4* e0 = (const float4*)(sE + c_l0 * K2_SH);
        const float4* e1 = (const float4*)(sE + c_l1 * K2_SH);
#pragma unroll 9
        for (int k = 0; k < D_ / 4; k++) {
            float4 h = h4[k];
            float4 x0 = e0[k];
            float4 x1 = e1[k];
            a0 = fmaf(h.x, x0.x, a0); a0 = fmaf(h.y, x0.y, a0);
            a0 = fmaf(h.z, x0.z, a0); a0 = fmaf(h.w, x0.w, a0);
            a1 = fmaf(h.x, x1.x, a1); a1 = fmaf(h.y, x1.y, a1);
            a1 = fmaf(h.z, x1.z, a1); a1 = fmaf(h.w, x1.w, a1);
        }
        if (c0 + c_l0 < C_) sS[o_l * K2_SS + c0 + c_l0] = a0;
        if (c0 + c_l1 < C_) sS[o_l * K2_SS + c0 + c_l1] = a1;
    }
    __syncthreads();

    // Softmax over C for each of the 32 rows: warp w handles rows 4w..4w+3
    int w = tid >> 5, lane = tid & 31;
    const unsigned char* mrow = mask + (size_t)b * C_;
#pragma unroll
    for (int q = 0; q < 4; q++) {
        int r = w * 4 + q;
        int og = o0 + r;
        if (og >= O_) continue;   // uniform within warp
        float mx = -CUDART_INF_F;
        for (int c = lane; c < C_; c += 32) {
            float v = mrow[c] ? -CUDART_INF_F : sS[r * K2_SS + c];
            mx = fmaxf(mx, v);
        }
#pragma unroll
        for (int off = 16; off; off >>= 1)
            mx = fmaxf(mx, __shfl_xor_sync(0xffffffffu, mx, off));
        float sum = 0.f;
        for (int c = lane; c < C_; c += 32) {
            float v = mrow[c] ? -CUDART_INF_F : sS[r * K2_SS + c];
            float e = __expf(v - mx);
            sS[r * K2_SS + c] = e;
            sum += e;
        }
#pragma unroll
        for (int off = 16; off; off >>= 1)
            sum += __shfl_xor_sync(0xffffffffu, sum, off);
        float inv = 1.f / sum;
        float* wout = g_w + ((size_t)b * O_ + og) * C_;
        for (int c = lane; c < C_; c += 32)
            wout[c] = sS[r * K2_SS + c] * inv;
    }
}

// ---------------------------------------------------------------------------
// Kernel 3: out[b,o,t] = sum_c w[b,o,c] * meg[b,c,t]
// Per-b GEMM: [270,273] x [273,4096]. Block tile 96(o) x 128(t) x 16(c),
// 256 threads, 6x8 micro-tile as 24 packed f32x2 accumulators (FFMA2).
// Weights stored DUPLICATED in smem ({w,w} pairs) so the inner loop is
// pure LDS.128 + fma.rn.f32x2 with zero pack/mov overhead.
// ---------------------------------------------------------------------------
#define BM 96
#define BN 128
#define BK 16
#define SWS 196   // sW row stride (floats); 192 used; 196*4 % 16 == 0
#define SMS 132   // sM row stride (floats); 132*4 % 16 == 0

#define FMA2(acc, av, bv) \
    asm("fma.rn.f32x2 %0, %1, %2, %0;" : "+l"(acc) : "l"(av), "l"(bv))

__global__ void __launch_bounds__(256) merge_kernel(
        const float* __restrict__ meg,
        float* __restrict__ out) {
    extern __shared__ float sm4[];
    float* sW = sm4;               // [BK][SWS]  duplicated weights
    float* sM = sm4 + BK * SWS;    // [BK][SMS]

    int t0 = blockIdx.x * BN;
    int o0 = blockIdx.y * BM;
    int b  = blockIdx.z;
    int tid = threadIdx.x;
    int tx = tid & 15;   // t group: outputs t0+4*tx..+3 and t0+64+4*tx..+3
    int ty = tid >> 4;   // o group: outputs o0+6*ty .. o0+6*ty+5

    unsigned long long acc[6][4];
#pragma unroll
    for (int i = 0; i < 6; i++)
#pragma unroll
        for (int j = 0; j < 4; j++) acc[i][j] = 0ull;

    const float* megb = meg + (size_t)b * C_ * T_;
    const float* wb = g_w + (size_t)b * O_ * C_;

    for (int c0 = 0; c0 < C_; c0 += BK) {
        __syncthreads();
        // Load W tile 96x16, duplicated: sW[k][2o..2o+1] = {w,w}
#pragma unroll
        for (int it = 0; it < 6; it++) {
            int idx = tid + it * 256;    // 0..1535
            int o = idx >> 4, k = idx & 15;
            int og = o0 + o, cg = c0 + k;
            float wv = (og < O_ && cg < C_) ? wb[(size_t)og * C_ + cg] : 0.f;
            *(float2*)(sW + k * SWS + 2 * o) = make_float2(wv, wv);
        }
        // Load M tile 16x128 (coalesced float4 rows)
#pragma unroll
        for (int j = 0; j < 2; j++) {
            int f4 = tid + j * 256;
            int row = f4 >> 5, col = (f4 & 31) << 2;
            int cg = c0 + row;
            float4 v = make_float4(0.f, 0.f, 0.f, 0.f);
            if (cg < C_) v = *(const float4*)(megb + (size_t)cg * T_ + t0 + col);
            *(float4*)(sM + row * SMS + col) = v;
        }
        __syncthreads();

#pragma unroll
        for (int k = 0; k < BK; k++) {
            const ulonglong2* wr = (const ulonglong2*)(sW + k * SWS + 12 * ty);
            const float* mrow = sM + k * SMS;
            ulonglong2 w01 = wr[0];
            ulonglong2 w23 = wr[1];
            ulonglong2 w45 = wr[2];
            ulonglong2 mA = *(const ulonglong2*)(mrow + 4 * tx);       // t 4tx..4tx+3
            ulonglong2 mB = *(const ulonglong2*)(mrow + 64 + 4 * tx);  // t 64+4tx..
            unsigned long long wv[6] = {w01.x, w01.y, w23.x, w23.y, w45.x, w45.y};
            unsigned long long mv[4] = {mA.x, mA.y, mB.x, mB.y};
#pragma unroll
            for (int i = 0; i < 6; i++)
#pragma unroll
                for (int j = 0; j < 4; j++)
                    FMA2(acc[i][j], wv[i], mv[j]);
        }
    }

    // Epilogue: 4 x STG.128 per o-row
#pragma unroll
    for (int i = 0; i < 6; i++) {
        int og = o0 + ty * 6 + i;
        if (og >= O_) continue;
        float* op = out + ((size_t)b * O_ + og) * T_ + t0;
        ulonglong2 sA, sB;
        sA.x = acc[i][0]; sA.y = acc[i][1];
        sB.x = acc[i][2]; sB.y = acc[i][3];
        *(ulonglong2*)(op + 4 * tx) = sA;
        *(ulonglong2*)(op + 64 + 4 * tx) = sB;
    }
}

// ---------------------------------------------------------------------------
extern "C" void kernel_launch(void* const* d_in, const int* in_sizes, int n_in,
                              void* d_out, int out_size) {
    const float* meg = (const float*)d_in[0];            // [B,C,T]
    const float* pos = (const float*)d_in[1];            // [B,C,2]
    const float* heads = (const float*)d_in[2];          // [O,D]
    const unsigned char* mask = (const unsigned char*)d_in[3];  // [B,C] bool
    float* out = (float*)d_out;                          // [B,O,T]

    // Kernel 2 needs 91,904 B dynamic smem (> 48 KB default)
    int smem2 = (K2_OT + K2_CH) * K2_SH * 4 + K2_OT * K2_SS * 4;
    cudaFuncSetAttribute(scores_kernel,
                         cudaFuncAttributeMaxDynamicSharedMemorySize, smem2);

    emb_kernel<<<B_ * C_, 144>>>(pos);
    scores_kernel<<<dim3(9, B_), 256, smem2>>>(heads, mask);

    int smem4 = (BK * SWS + BK * SMS) * 4;   // ~21 KB
    merge_kernel<<<dim3(T_ / BN, (O_ + BM - 1) / BM, B_), 256, smem4>>>(meg, out);
}

// round 3
// speedup vs baseline: 2.4021x; 2.4021x over previous
#include <cuda_runtime.h>
#include <math_constants.h>
#include <cstdint>

#define B_ 32
#define C_ 273
#define T_ 4096
#define O_ 270
#define D_ 288
#define OPAD 288   // padded o rows of g_w
#define WPAD 288   // padded C stride of g_w

// Device scratch (allocation-free rule: __device__ globals)
__device__ float g_emb[B_ * C_ * D_];          // [B][C][288]
__device__ float g_w[B_ * OPAD * WPAD];        // [B][288][288], tf32-rounded, zero padded

// round-to-nearest fp32 -> tf32 bit pattern
__device__ __forceinline__ uint32_t rn_tf32(float x) {
    return (__float_as_uint(x) + 0x1000u) & 0xFFFFE000u;
}
__device__ __forceinline__ uint32_t rn_tf32_u(uint32_t u) {
    return (u + 0x1000u) & 0xFFFFE000u;
}
__device__ __forceinline__ uint32_t smem_u32(const void* p) {
    uint32_t a;
    asm("{ .reg .u64 t; cvta.to.shared.u64 t, %1; cvt.u32.u64 %0, t; }"
        : "=r"(a) : "l"(p));
    return a;
}

#define CP16(dst, src, ssz) \
    asm volatile("cp.async.cg.shared.global [%0], [%1], 16, %2;" \
                 :: "r"(dst), "l"(src), "r"(ssz) : "memory")
#define CP_COMMIT() asm volatile("cp.async.commit_group;" ::: "memory")
#define CP_WAIT(n)  asm volatile("cp.async.wait_group %0;" :: "n"(n) : "memory")

#define MMA_TF32(d, a, bq) \
    asm volatile("mma.sync.aligned.m16n8k8.row.col.f32.tf32.tf32.f32 " \
        "{%0,%1,%2,%3}, {%4,%5,%6,%7}, {%8,%9}, {%0,%1,%2,%3};" \
        : "+f"((d)[0]), "+f"((d)[1]), "+f"((d)[2]), "+f"((d)[3]) \
        : "r"((a)[0]), "r"((a)[1]), "r"((a)[2]), "r"((a)[3]), \
          "r"((bq)[0]), "r"((bq)[1]))

// ---------------------------------------------------------------------------
// Kernel 1: Fourier embedding. One block per (b,c), 144 threads.
// ---------------------------------------------------------------------------
__global__ void emb_kernel(const float* __restrict__ pos) {
    int bc = blockIdx.x;
    int i = threadIdx.x;
    float px = pos[bc * 2 + 0] + 0.1f;
    float py = pos[bc * 2 + 1] + 0.1f;
    const float sc = 6.283185307179586f / 1.2f;
    int fx = i / 12;
    int fy = i - fx * 12;
    float loc = px * (sc * (float)fx) + py * (sc * (float)fy);
    float s, c;
    sincosf(loc, &s, &c);
    g_emb[bc * D_ + i] = c;
    g_emb[bc * D_ + 144 + i] = s;
}

// ---------------------------------------------------------------------------
// Kernel 2: scores + softmax -> g_w (tf32-rounded, zero-padded to [288][288])
// ---------------------------------------------------------------------------
#define K2_OT 32
#define K2_CH 16
#define K2_SH 292
#define K2_SS 280

__global__ void __launch_bounds__(256) scores_kernel(
        const float* __restrict__ heads,
        const unsigned char* __restrict__ mask) {
    extern __shared__ float sm2[];
    float* sH = sm2;
    float* sE = sm2 + K2_OT * K2_SH;
    float* sS = sm2 + (K2_OT + K2_CH) * K2_SH;

    int b = blockIdx.y;
    int o0 = blockIdx.x * K2_OT;
    int tid = threadIdx.x;

    for (int idx = tid; idx < K2_OT * D_; idx += 256) {
        int o = idx / D_, d = idx - o * D_;
        int og = o0 + o;
        sH[o * K2_SH + d] = (og < O_) ? heads[og * D_ + d] : 0.f;
    }

    int o_l = tid & 31;
    int cp = tid >> 5;
    int c_l0 = cp * 2, c_l1 = cp * 2 + 1;

    for (int c0 = 0; c0 < C_; c0 += K2_CH) {
        __syncthreads();
        for (int idx = tid; idx < K2_CH * D_; idx += 256) {
            int cl = idx / D_, d = idx - cl * D_;
            int cg = c0 + cl;
            sE[cl * K2_SH + d] = (cg < C_) ? g_emb[((size_t)b * C_ + cg) * D_ + d] : 0.f;
        }
        __syncthreads();

        float a0 = 0.f, a1 = 0.f;
        const float4* h4 = (const float4*)(sH + o_l * K2_SH);
        const float4* e0 = (const float4*)(sE + c_l0 * K2_SH);
        const float4* e1 = (const float4*)(sE + c_l1 * K2_SH);
#pragma unroll 9
        for (int k = 0; k < D_ / 4; k++) {
            float4 h = h4[k];
            float4 x0 = e0[k];
            float4 x1 = e1[k];
            a0 = fmaf(h.x, x0.x, a0); a0 = fmaf(h.y, x0.y, a0);
            a0 = fmaf(h.z, x0.z, a0); a0 = fmaf(h.w, x0.w, a0);
            a1 = fmaf(h.x, x1.x, a1); a1 = fmaf(h.y, x1.y, a1);
            a1 = fmaf(h.z, x1.z, a1); a1 = fmaf(h.w, x1.w, a1);
        }
        if (c0 + c_l0 < C_) sS[o_l * K2_SS + c0 + c_l0] = a0;
        if (c0 + c_l1 < C_) sS[o_l * K2_SS + c0 + c_l1] = a1;
    }
    __syncthreads();

    int w = tid >> 5, lane = tid & 31;
    const unsigned char* mrow = mask + (size_t)b * C_;
#pragma unroll
    for (int q = 0; q < 4; q++) {
        int r = w * 4 + q;
        int og = o0 + r;
        float* wout = g_w + ((size_t)b * OPAD + og) * WPAD;
        if (og >= O_) {   // zero pad rows [270, 288)
            for (int c = lane; c < WPAD; c += 32) wout[c] = 0.f;
            continue;
        }
        float mx = -CUDART_INF_F;
        for (int c = lane; c < C_; c += 32) {
            float v = mrow[c] ? -CUDART_INF_F : sS[r * K2_SS + c];
            mx = fmaxf(mx, v);
        }
#pragma unroll
        for (int off = 16; off; off >>= 1)
            mx = fmaxf(mx, __shfl_xor_sync(0xffffffffu, mx, off));
        float sum = 0.f;
        for (int c = lane; c < C_; c += 32) {
            float v = mrow[c] ? -CUDART_INF_F : sS[r * K2_SS + c];
            float e = __expf(v - mx);
            sS[r * K2_SS + c] = e;
            sum += e;
        }
#pragma unroll
        for (int off = 16; off; off >>= 1)
            sum += __shfl_xor_sync(0xffffffffu, sum, off);
        float inv = 1.f / sum;
        for (int c = lane; c < WPAD; c += 32) {
            float v = (c < C_) ? sS[r * K2_SS + c] * inv : 0.f;
            wout[c] = __uint_as_float(rn_tf32(v));   // tf32-RN at source
        }
    }
}

// ---------------------------------------------------------------------------
// Kernel 3: tf32 mma.sync merge GEMM.
// Per b: OUT[o,t] = W[o,c] x MEG[c,t].  CTA tile 96(o) x 128(t) x 32(c).
// 8 warps as 2(m) x 4(n); warp tile 48x32 = 3x4 m16n8k8 MMAs per k-step.
// smem: sW[2][96][36] (m-major, stride 36 => conflict-free A frags),
//       sM[2][32][136] (k-major, stride 136 => conflict-free B frags).
// cp.async double-buffered; ZFILL pads c in [273,288).
// ---------------------------------------------------------------------------
#define BM 96
#define BN 128
#define BK 32
#define SWSTR 36
#define SMSTR 136
#define NCH 9
#define SW_BYTES (BM * SWSTR * 4)   // 13824
#define SM_BYTES (BK * SMSTR * 4)   // 17408

__global__ void __launch_bounds__(256) merge_mma(
        const float* __restrict__ meg,
        float* __restrict__ out) {
    extern __shared__ float sm[];
    float* sW = sm;                        // [2][BM][SWSTR]
    float* sM = sm + 2 * BM * SWSTR;       // [2][BK][SMSTR]
    uint32_t sWb = smem_u32(sW), sMb = smem_u32(sM);

    int tid = threadIdx.x;
    int wid = tid >> 5, lane = tid & 31;
    int wm = wid >> 2, wn = wid & 3;
    int lq = lane >> 2, lr = lane & 3;     // quad row / in-quad col
    int t0 = blockIdx.x * BN;
    int o0 = blockIdx.y * BM;
    int b = blockIdx.z;

    const float* megb = meg + (size_t)b * C_ * T_;
    const float* wb = g_w + (size_t)b * OPAD * WPAD + (size_t)o0 * WPAD;

    float acc[3][4][4];
#pragma unroll
    for (int i = 0; i < 3; i++)
#pragma unroll
        for (int j = 0; j < 4; j++)
#pragma unroll
            for (int r = 0; r < 4; r++) acc[i][j][r] = 0.f;

    // --- async chunk loader ---
    auto load_chunk = [&](int ch) {
        int c0 = ch * BK;
        int st = ch & 1;
        uint32_t wdst = sWb + st * SW_BYTES;
        uint32_t mdst = sMb + st * SM_BYTES;
#pragma unroll
        for (int it = 0; it < 3; it++) {        // 96 rows x 8 float4
            int idx = tid + it * 256;
            int row = idx >> 3, q = idx & 7;
            const float* src = wb + (size_t)row * WPAD + c0 + (q << 2);
            CP16(wdst + (row * SWSTR + (q << 2)) * 4, src, 16);
        }
#pragma unroll
        for (int it = 0; it < 4; it++) {        // 32 rows x 32 float4
            int idx = tid + it * 256;
            int row = idx >> 5, q = idx & 31;
            int c = c0 + row;
            int cc = (c < C_) ? c : (C_ - 1);
            const float* src = megb + (size_t)cc * T_ + t0 + (q << 2);
            CP16(mdst + (row * SMSTR + (q << 2)) * 4, src, (c < C_) ? 16 : 0);
        }
        CP_COMMIT();
    };

    load_chunk(0);
    for (int ch = 0; ch < NCH; ch++) {
        if (ch + 1 < NCH) { load_chunk(ch + 1); CP_WAIT(1); }
        else             { CP_WAIT(0); }
        __syncthreads();

        int st = ch & 1;
        const float* w = sW + st * BM * SWSTR;
        const float* m = sM + st * BK * SMSTR;

#pragma unroll
        for (int kk = 0; kk < 4; kk++) {
            int k0 = kk * 8;
            uint32_t afr[3][4];
#pragma unroll
            for (int mt = 0; mt < 3; mt++) {
                const float* base = w + (wm * 48 + mt * 16 + lq) * SWSTR + k0 + lr;
                afr[mt][0] = __float_as_uint(base[0]);
                afr[mt][1] = __float_as_uint(base[8 * SWSTR]);
                afr[mt][2] = __float_as_uint(base[4]);
                afr[mt][3] = __float_as_uint(base[8 * SWSTR + 4]);
            }
            uint32_t bfr[4][2];
#pragma unroll
            for (int nt = 0; nt < 4; nt++) {
                const float* base = m + (k0 + lr) * SMSTR + wn * 32 + nt * 8 + lq;
                bfr[nt][0] = rn_tf32_u(__float_as_uint(base[0]));
                bfr[nt][1] = rn_tf32_u(__float_as_uint(base[4 * SMSTR]));
            }
#pragma unroll
            for (int mt = 0; mt < 3; mt++)
#pragma unroll
                for (int nt = 0; nt < 4; nt++)
                    MMA_TF32(acc[mt][nt], afr[mt], bfr[nt]);
        }
        __syncthreads();
    }

    // --- epilogue: d0,d1 -> (row, 2c), d2,d3 -> (row+8, 2c) ---
#pragma unroll
    for (int mt = 0; mt < 3; mt++) {
        int obase = o0 + wm * 48 + mt * 16 + lq;
#pragma unroll
        for (int half = 0; half < 2; half++) {
            int og = obase + half * 8;
            if (og < O_) {
                float* op = out + ((size_t)b * O_ + og) * T_ + t0 + wn * 32 + lr * 2;
#pragma unroll
                for (int nt = 0; nt < 4; nt++) {
                    float2 v = make_float2(acc[mt][nt][half * 2],
                                           acc[mt][nt][half * 2 + 1]);
                    *(float2*)(op + nt * 8) = v;
                }
            }
        }
    }
}

// ---------------------------------------------------------------------------
extern "C" void kernel_launch(void* const* d_in, const int* in_sizes, int n_in,
                              void* d_out, int out_size) {
    const float* meg = (const float*)d_in[0];
    const float* pos = (const float*)d_in[1];
    const float* heads = (const float*)d_in[2];
    const unsigned char* mask = (const unsigned char*)d_in[3];
    float* out = (float*)d_out;

    int smem2 = (K2_OT + K2_CH) * K2_SH * 4 + K2_OT * K2_SS * 4;
    cudaFuncSetAttribute(scores_kernel,
                         cudaFuncAttributeMaxDynamicSharedMemorySize, smem2);

    int smem3 = 2 * SW_BYTES + 2 * SM_BYTES;   // 62464 B
    cudaFuncSetAttribute(merge_mma,
                         cudaFuncAttributeMaxDynamicSharedMemorySize, smem3);

    emb_kernel<<<B_ * C_, 144>>>(pos);
    scores_kernel<<<dim3(9, B_), 256, smem2>>>(heads, mask);
    merge_mma<<<dim3(T_ / BN, (O_ + BM - 1) / BM, B_), 256, smem3>>>(meg, out);
}

// round 4
// speedup vs baseline: 2.7962x; 1.1641x over previous
#include <cuda_runtime.h>
#include <cuda_fp16.h>
#include <math_constants.h>
#include <cstdint>

#define B_ 32
#define C_ 273
#define T_ 4096
#define O_ 270
#define D_ 288
#define OPAD 288
#define WPAD 288

// Device scratch (allocation-free rule: __device__ globals)
__device__ float g_emb[B_ * C_ * D_];          // [B][C][288]
__device__ __half g_w[B_ * OPAD * WPAD];       // [B][288][288] fp16, zero padded

__device__ __forceinline__ uint32_t smem_u32(const void* p) {
    uint32_t a;
    asm("{ .reg .u64 t; cvta.to.shared.u64 t, %1; cvt.u32.u64 %0, t; }"
        : "=r"(a) : "l"(p));
    return a;
}

#define CP16(dst, src) \
    asm volatile("cp.async.cg.shared.global [%0], [%1], 16;" \
                 :: "r"(dst), "l"(src) : "memory")
#define CP_COMMIT() asm volatile("cp.async.commit_group;" ::: "memory")
#define CP_WAIT(n)  asm volatile("cp.async.wait_group %0;" :: "n"(n) : "memory")

#define LDSM4(r, addr) \
    asm volatile("ldmatrix.sync.aligned.m8n8.x4.shared.b16 {%0,%1,%2,%3}, [%4];" \
        : "=r"((r)[0]), "=r"((r)[1]), "=r"((r)[2]), "=r"((r)[3]) : "r"(addr))
#define LDSM4T(r, addr) \
    asm volatile("ldmatrix.sync.aligned.m8n8.x4.trans.shared.b16 {%0,%1,%2,%3}, [%4];" \
        : "=r"((r)[0]), "=r"((r)[1]), "=r"((r)[2]), "=r"((r)[3]) : "r"(addr))

#define MMA_F16(d, a, b) \
    asm volatile("mma.sync.aligned.m16n8k16.row.col.f32.f16.f16.f32 " \
        "{%0,%1,%2,%3}, {%4,%5,%6,%7}, {%8,%9}, {%0,%1,%2,%3};" \
        : "+f"((d)[0]), "+f"((d)[1]), "+f"((d)[2]), "+f"((d)[3]) \
        : "r"((a)[0]), "r"((a)[1]), "r"((a)[2]), "r"((a)[3]), \
          "r"((b)[0]), "r"((b)[1]))

// packed f32x2 FMA
#define FMA2(acc, av, bv) \
    asm("fma.rn.f32x2 %0, %1, %2, %0;" : "+l"(acc) : "l"(av), "l"(bv))

// ---------------------------------------------------------------------------
// Kernel 1: Fourier embedding. One block per (b,c), 144 threads.
// ---------------------------------------------------------------------------
__global__ void emb_kernel(const float* __restrict__ pos) {
    int bc = blockIdx.x;
    int i = threadIdx.x;
    float px = pos[bc * 2 + 0] + 0.1f;
    float py = pos[bc * 2 + 1] + 0.1f;
    const float sc = 6.283185307179586f / 1.2f;
    int fx = i / 12;
    int fy = i - fx * 12;
    float loc = px * (sc * (float)fx) + py * (sc * (float)fy);
    float s, c;
    sincosf(loc, &s, &c);
    g_emb[bc * D_ + i] = c;
    g_emb[bc * D_ + 144 + i] = s;
}

// ---------------------------------------------------------------------------
// Kernel 2: scores + softmax -> g_w (fp16, zero-padded to [288][288])
// Inner dot product uses packed f32x2 FMAs (half the FMA issue count).
// ---------------------------------------------------------------------------
#define K2_OT 32
#define K2_CH 16
#define K2_SH 292
#define K2_SS 280

__global__ void __launch_bounds__(256) scores_kernel(
        const float* __restrict__ heads,
        const unsigned char* __restrict__ mask) {
    extern __shared__ float sm2[];
    float* sH = sm2;
    float* sE = sm2 + K2_OT * K2_SH;
    float* sS = sm2 + (K2_OT + K2_CH) * K2_SH;

    int b = blockIdx.y;
    int o0 = blockIdx.x * K2_OT;
    int tid = threadIdx.x;

    for (int idx = tid; idx < K2_OT * D_; idx += 256) {
        int o = idx / D_, d = idx - o * D_;
        int og = o0 + o;
        sH[o * K2_SH + d] = (og < O_) ? heads[og * D_ + d] : 0.f;
    }

    int o_l = tid & 31;
    int cp = tid >> 5;
    int c_l0 = cp * 2, c_l1 = cp * 2 + 1;

    for (int c0 = 0; c0 < C_; c0 += K2_CH) {
        __syncthreads();
        for (int idx = tid; idx < K2_CH * D_; idx += 256) {
            int cl = idx / D_, d = idx - cl * D_;
            int cg = c0 + cl;
            sE[cl * K2_SH + d] = (cg < C_) ? g_emb[((size_t)b * C_ + cg) * D_ + d] : 0.f;
        }
        __syncthreads();

        unsigned long long A0 = 0ull, A1 = 0ull;
        const ulonglong2* h2 = (const ulonglong2*)(sH + o_l * K2_SH);
        const ulonglong2* e0 = (const ulonglong2*)(sE + c_l0 * K2_SH);
        const ulonglong2* e1 = (const ulonglong2*)(sE + c_l1 * K2_SH);
#pragma unroll 9
        for (int k = 0; k < D_ / 4; k++) {
            ulonglong2 h = h2[k];
            ulonglong2 x0 = e0[k];
            ulonglong2 x1 = e1[k];
            FMA2(A0, h.x, x0.x);
            FMA2(A0, h.y, x0.y);
            FMA2(A1, h.x, x1.x);
            FMA2(A1, h.y, x1.y);
        }
        float2 f0 = *(float2*)&A0;
        float2 f1 = *(float2*)&A1;
        if (c0 + c_l0 < C_) sS[o_l * K2_SS + c0 + c_l0] = f0.x + f0.y;
        if (c0 + c_l1 < C_) sS[o_l * K2_SS + c0 + c_l1] = f1.x + f1.y;
    }
    __syncthreads();

    int w = tid >> 5, lane = tid & 31;
    const unsigned char* mrow = mask + (size_t)b * C_;
#pragma unroll
    for (int q = 0; q < 4; q++) {
        int r = w * 4 + q;
        int og = o0 + r;
        __half* wout = g_w + ((size_t)b * OPAD + og) * WPAD;
        if (og >= O_) {
            for (int c = lane; c < WPAD; c += 32) wout[c] = __float2half_rn(0.f);
            continue;
        }
        float mx = -CUDART_INF_F;
        for (int c = lane; c < C_; c += 32) {
            float v = mrow[c] ? -CUDART_INF_F : sS[r * K2_SS + c];
            mx = fmaxf(mx, v);
        }
#pragma unroll
        for (int off = 16; off; off >>= 1)
            mx = fmaxf(mx, __shfl_xor_sync(0xffffffffu, mx, off));
        float sum = 0.f;
        for (int c = lane; c < C_; c += 32) {
            float v = mrow[c] ? -CUDART_INF_F : sS[r * K2_SS + c];
            float e = __expf(v - mx);
            sS[r * K2_SS + c] = e;
            sum += e;
        }
#pragma unroll
        for (int off = 16; off; off >>= 1)
            sum += __shfl_xor_sync(0xffffffffu, sum, off);
        float inv = 1.f / sum;
        for (int c = lane; c < WPAD; c += 32) {
            float v = (c < C_) ? sS[r * K2_SS + c] * inv : 0.f;
            wout[c] = __float2half_rn(v);
        }
    }
}

// ---------------------------------------------------------------------------
// Kernel 3: fp16 mma.sync merge GEMM.
// Per b: OUT[o,t] = W[o,c] x MEG[c,t]. CTA tile 96(o) x 128(t) x 32(c).
// 8 warps as 2(m) x 4(n); warp tile 48x32 = 3x4 m16n8k16 MMAs per k16-step.
// smem (halves): sW[2][96][40] (stride 80B -> ldmatrix conflict-free),
//                sM[2][32][136] (stride 272B -> ldmatrix.trans conflict-free).
// W via cp.async (already fp16); meg via LDG.128 + cvt + STS.64, reg-prefetched.
// ---------------------------------------------------------------------------
#define BM 96
#define BN 128
#define BK 32
#define SWSTR 40     // halves
#define SMSTR 136    // halves
#define NCH 9
#define SW_BYTES (BM * SWSTR * 2)   // 7680
#define SM_BYTES (BK * SMSTR * 2)   // 8704

__global__ void __launch_bounds__(256, 2) merge_mma(
        const float* __restrict__ meg,
        float* __restrict__ out) {
    extern __shared__ __half smh[];
    __half* sW = smh;                       // [2][96][SWSTR]
    __half* sM = smh + 2 * BM * SWSTR;      // [2][32][SMSTR]
    uint32_t sWb = smem_u32(sW), sMb = smem_u32(sM);

    int tid = threadIdx.x;
    int wid = tid >> 5, lane = tid & 31;
    int wm = wid >> 2, wn = wid & 3;
    int lq = lane >> 2, lr = lane & 3;
    int t0 = blockIdx.x * BN;
    int o0 = blockIdx.y * BM;
    int b = blockIdx.z;

    const float* megb = meg + (size_t)b * C_ * T_;
    const __half* wb = g_w + (size_t)b * OPAD * WPAD + (size_t)o0 * WPAD;

    // per-lane ldmatrix base offsets
    uint32_t a_row = (uint32_t)(wm * 48 + (lane & 15));
    uint32_t a_ksel = (uint32_t)((lane >> 4) * 8);
    uint32_t b_row = (uint32_t)(lane & 15);
    uint32_t b_nsel = (uint32_t)(wn * 32 + (lane >> 4) * 8);

    // meg loader indices: 4 float4 units per thread per chunk
    int m_row[4], m_q[4];
#pragma unroll
    for (int it = 0; it < 4; it++) {
        int idx = tid + it * 256;
        m_row[it] = idx >> 5;        // 0..31 (c within chunk)
        m_q[it] = idx & 31;          // float4 column
    }

    float acc[3][4][4];
#pragma unroll
    for (int i = 0; i < 3; i++)
#pragma unroll
        for (int j = 0; j < 4; j++)
#pragma unroll
            for (int r = 0; r < 4; r++) acc[i][j][r] = 0.f;

    // W cp.async loader: 384 16B units (96 rows x 4)
    auto loadW = [&](int ch, int st) {
        uint32_t wdst = sWb + st * SW_BYTES;
        int c0 = ch * BK;
        if (tid < 128) {
#pragma unroll
            for (int it = 0; it < 3; it++) {
                int idx = tid + it * 128;       // 0..383
                int row = idx >> 2, qq = idx & 3;
                const __half* src = wb + (size_t)row * WPAD + c0 + qq * 8;
                CP16(wdst + (uint32_t)(row * (SWSTR * 2) + qq * 16), src);
            }
        }
        CP_COMMIT();
    };
    // meg gmem->regs
    auto loadM = [&](int ch, float4* v) {
        int c0 = ch * BK;
#pragma unroll
        for (int it = 0; it < 4; it++) {
            int c = c0 + m_row[it];
            if (c < C_)
                v[it] = *(const float4*)(megb + (size_t)c * T_ + t0 + (m_q[it] << 2));
            else
                v[it] = make_float4(0.f, 0.f, 0.f, 0.f);
        }
    };
    // regs->smem (fp16)
    auto stsM = [&](int st, const float4* v) {
        __half* dst = sM + st * BK * SMSTR;
#pragma unroll
        for (int it = 0; it < 4; it++) {
            __half2 h01 = __floats2half2_rn(v[it].x, v[it].y);
            __half2 h23 = __floats2half2_rn(v[it].z, v[it].w);
            uint2 u;
            u.x = *(uint32_t*)&h01;
            u.y = *(uint32_t*)&h23;
            *(uint2*)(dst + m_row[it] * SMSTR + (m_q[it] << 2)) = u;
        }
    };

    // prologue: chunk 0
    float4 vreg[4];
    loadW(0, 0);
    loadM(0, vreg);
    stsM(0, vreg);

    for (int ch = 0; ch < NCH; ch++) {
        int st = ch & 1;
        if (ch + 1 < NCH) {
            loadM(ch + 1, vreg);          // long-latency LDG first
            loadW(ch + 1, st ^ 1);
            CP_WAIT(1);                   // W(ch) complete
        } else {
            CP_WAIT(0);
        }
        __syncthreads();                  // all STS(ch) + W(ch) visible

        uint32_t wbase = sWb + st * SW_BYTES;
        uint32_t mbase = sMb + st * SM_BYTES;

#pragma unroll
        for (int ks = 0; ks < 2; ks++) {
            uint32_t afr[3][4];
#pragma unroll
            for (int mt = 0; mt < 3; mt++)
                LDSM4(afr[mt], wbase + (a_row + mt * 16) * (SWSTR * 2)
                               + (ks * 16 + a_ksel) * 2);
            uint32_t bfr[2][4];
#pragma unroll
            for (int ldm = 0; ldm < 2; ldm++)
                LDSM4T(bfr[ldm], mbase + (ks * 16 + b_row) * (SMSTR * 2)
                                 + (b_nsel + ldm * 16) * 2);
#pragma unroll
            for (int mt = 0; mt < 3; mt++)
#pragma unroll
                for (int nt = 0; nt < 4; nt++)
                    MMA_F16(acc[mt][nt], afr[mt], &bfr[nt >> 1][(nt & 1) * 2]);
        }

        if (ch + 1 < NCH) stsM(st ^ 1, vreg);
    }

    // epilogue: d0,d1 -> (row, 2c..), d2,d3 -> (row+8, 2c..)
#pragma unroll
    for (int mt = 0; mt < 3; mt++) {
        int obase = o0 + wm * 48 + mt * 16 + lq;
#pragma unroll
        for (int half = 0; half < 2; half++) {
            int og = obase + half * 8;
            if (og < O_) {
                float* op = out + ((size_t)b * O_ + og) * T_ + t0 + wn * 32 + lr * 2;
#pragma unroll
                for (int nt = 0; nt < 4; nt++) {
                    float2 v = make_float2(acc[mt][nt][half * 2],
                                           acc[mt][nt][half * 2 + 1]);
                    *(float2*)(op + nt * 8) = v;
                }
            }
        }
    }
}

// ---------------------------------------------------------------------------
extern "C" void kernel_launch(void* const* d_in, const int* in_sizes, int n_in,
                              void* d_out, int out_size) {
    const float* meg = (const float*)d_in[0];
    const float* pos = (const float*)d_in[1];
    const float* heads = (const float*)d_in[2];
    const unsigned char* mask = (const unsigned char*)d_in[3];
    float* out = (float*)d_out;

    int smem2 = (K2_OT + K2_CH) * K2_SH * 4 + K2_OT * K2_SS * 4;
    cudaFuncSetAttribute(scores_kernel,
                         cudaFuncAttributeMaxDynamicSharedMemorySize, smem2);

    int smem3 = 2 * SW_BYTES + 2 * SM_BYTES;   // 32768 B
    cudaFuncSetAttribute(merge_mma,
                         cudaFuncAttributeMaxDynamicSharedMemorySize, smem3);

    emb_kernel<<<B_ * C_, 144>>>(pos);
    scores_kernel<<<dim3(9, B_), 256, smem2>>>(heads, mask);
    merge_mma<<<dim3(T_ / BN, (O_ + BM - 1) / BM, B_), 256, smem3>>>(meg, out);
}

// round 5
// speedup vs baseline: 4.8059x; 1.7187x over previous
#include <cuda_runtime.h>
#include <cuda_fp16.h>
#include <math_constants.h>
#include <cstdint>

#define B_ 32
#define C_ 273
#define T_ 4096
#define O_ 270
#define D_ 288

// Device scratch (allocation-free rule: __device__ globals)
__device__ float g_emb[B_ * C_ * D_];        // [B][C][288]
__device__ float g_s[B_ * 288 * 288];        // scores, padded [B][288o][288c]
__device__ __half g_w[B_ * 288 * 288];       // softmax weights fp16, padded

__device__ __forceinline__ uint32_t smem_u32(const void* p) {
    uint32_t a;
    asm("{ .reg .u64 t; cvta.to.shared.u64 t, %1; cvt.u32.u64 %0, t; }"
        : "=r"(a) : "l"(p));
    return a;
}
__device__ __forceinline__ uint32_t rn_tf32_u(uint32_t u) {
    return (u + 0x1000u) & 0xFFFFE000u;
}

#define CP16(dst, src) \
    asm volatile("cp.async.cg.shared.global [%0], [%1], 16;" \
                 :: "r"(dst), "l"(src) : "memory")
#define CP16Z(dst, src, ssz) \
    asm volatile("cp.async.cg.shared.global [%0], [%1], 16, %2;" \
                 :: "r"(dst), "l"(src), "r"(ssz) : "memory")
#define CP_COMMIT() asm volatile("cp.async.commit_group;" ::: "memory")
#define CP_WAIT(n)  asm volatile("cp.async.wait_group %0;" :: "n"(n) : "memory")

#define LDSM4(r, addr) \
    asm volatile("ldmatrix.sync.aligned.m8n8.x4.shared.b16 {%0,%1,%2,%3}, [%4];" \
        : "=r"((r)[0]), "=r"((r)[1]), "=r"((r)[2]), "=r"((r)[3]) : "r"(addr))
#define LDSM4T(r, addr) \
    asm volatile("ldmatrix.sync.aligned.m8n8.x4.trans.shared.b16 {%0,%1,%2,%3}, [%4];" \
        : "=r"((r)[0]), "=r"((r)[1]), "=r"((r)[2]), "=r"((r)[3]) : "r"(addr))

#define MMA_F16(d, a, b) \
    asm volatile("mma.sync.aligned.m16n8k16.row.col.f32.f16.f16.f32 " \
        "{%0,%1,%2,%3}, {%4,%5,%6,%7}, {%8,%9}, {%0,%1,%2,%3};" \
        : "+f"((d)[0]), "+f"((d)[1]), "+f"((d)[2]), "+f"((d)[3]) \
        : "r"((a)[0]), "r"((a)[1]), "r"((a)[2]), "r"((a)[3]), \
          "r"((b)[0]), "r"((b)[1]))

#define MMA_TF32(d, a, bq) \
    asm volatile("mma.sync.aligned.m16n8k8.row.col.f32.tf32.tf32.f32 " \
        "{%0,%1,%2,%3}, {%4,%5,%6,%7}, {%8,%9}, {%0,%1,%2,%3};" \
        : "+f"((d)[0]), "+f"((d)[1]), "+f"((d)[2]), "+f"((d)[3]) \
        : "r"((a)[0]), "r"((a)[1]), "r"((a)[2]), "r"((a)[3]), \
          "r"((bq)[0]), "r"((bq)[1]))

// ---------------------------------------------------------------------------
// Kernel 1: Fourier embedding. Flat grid, one sincos per thread.
// |loc| <= ~138 rad; __sincosf abs err ~1e-5 there — harmless pre-softmax.
// ---------------------------------------------------------------------------
__global__ void __launch_bounds__(256) emb_kernel(const float* __restrict__ pos) {
    int g = blockIdx.x * 256 + threadIdx.x;    // 0 .. B*C*144-1 (exact)
    int bc = g / 144;
    int i = g - bc * 144;
    float px = pos[bc * 2 + 0] + 0.1f;
    float py = pos[bc * 2 + 1] + 0.1f;
    const float sc = 6.283185307179586f / 1.2f;
    int fx = i / 12;
    int fy = i - fx * 12;
    float loc = px * (sc * (float)fx) + py * (sc * (float)fy);
    float s, c;
    __sincosf(loc, &s, &c);
    g_emb[bc * D_ + i] = c;
    g_emb[bc * D_ + 144 + i] = s;
}

// ---------------------------------------------------------------------------
// Kernel 2: scores GEMM (tf32 mma.sync).
// S[b,o,c] = sum_d heads[o,d] * emb[b,c,d].  A=heads row-major, B=emb col-major
// (both k-major!).  Block tile 96(o) x 96(c) x 32(d); warps 2x4, warp 48x24.
// Output to g_s padded [288][288] — zero guards anywhere.
// ---------------------------------------------------------------------------
#define SSTR 36

__global__ void __launch_bounds__(256) scores_gemm(
        const float* __restrict__ heads) {
    extern __shared__ float ssm[];
    float* sH = ssm;                      // [2][96][36]
    float* sE = ssm + 2 * 96 * SSTR;      // [2][96][36]
    uint32_t sHb = smem_u32(sH), sEb = smem_u32(sE);

    int tid = threadIdx.x;
    int wid = tid >> 5, lane = tid & 31;
    int wm = wid >> 2, wn = wid & 3;
    int lq = lane >> 2, lr = lane & 3;
    int cc0 = blockIdx.x * 96;
    int o0 = blockIdx.y * 96;
    int b = blockIdx.z;

    const float* embb = g_emb + (size_t)b * C_ * D_;

    float acc[3][3][4];
#pragma unroll
    for (int i = 0; i < 3; i++)
#pragma unroll
        for (int j = 0; j < 3; j++)
#pragma unroll
            for (int r = 0; r < 4; r++) acc[i][j][r] = 0.f;

    auto load_chunk = [&](int ch) {
        int d0 = ch * 32;
        int st = ch & 1;
        uint32_t hdst = sHb + st * (96 * SSTR * 4);
        uint32_t edst = sEb + st * (96 * SSTR * 4);
#pragma unroll
        for (int it = 0; it < 3; it++) {       // 96 rows x 8 float4
            int idx = tid + it * 256;
            int row = idx >> 3, q = idx & 7;
            int og = o0 + row;
            const float* src = heads + (size_t)(og < O_ ? og : 0) * D_ + d0 + (q << 2);
            CP16Z(hdst + (row * SSTR + (q << 2)) * 4, src, (og < O_) ? 16 : 0);
            int cg = cc0 + row;
            const float* esrc = embb + (size_t)(cg < C_ ? cg : 0) * D_ + d0 + (q << 2);
            CP16Z(edst + (row * SSTR + (q << 2)) * 4, esrc, (cg < C_) ? 16 : 0);
        }
        CP_COMMIT();
    };

    load_chunk(0);
    for (int ch = 0; ch < 9; ch++) {
        if (ch + 1 < 9) { load_chunk(ch + 1); CP_WAIT(1); }
        else            { CP_WAIT(0); }
        __syncthreads();

        int st = ch & 1;
        const float* h = sH + st * 96 * SSTR;
        const float* e = sE + st * 96 * SSTR;

#pragma unroll
        for (int kk = 0; kk < 4; kk++) {
            int k0 = kk * 8;
            uint32_t afr[3][4];
#pragma unroll
            for (int mt = 0; mt < 3; mt++) {
                const float* base = h + (wm * 48 + mt * 16 + lq) * SSTR + k0 + lr;
                afr[mt][0] = rn_tf32_u(__float_as_uint(base[0]));
                afr[mt][1] = rn_tf32_u(__float_as_uint(base[8 * SSTR]));
                afr[mt][2] = rn_tf32_u(__float_as_uint(base[4]));
                afr[mt][3] = rn_tf32_u(__float_as_uint(base[8 * SSTR + 4]));
            }
            uint32_t bfr[3][2];
#pragma unroll
            for (int nt = 0; nt < 3; nt++) {
                const float* base = e + (wn * 24 + nt * 8 + lq) * SSTR + k0 + lr;
                bfr[nt][0] = rn_tf32_u(__float_as_uint(base[0]));
                bfr[nt][1] = rn_tf32_u(__float_as_uint(base[4]));
            }
#pragma unroll
            for (int mt = 0; mt < 3; mt++)
#pragma unroll
                for (int nt = 0; nt < 3; nt++)
                    MMA_TF32(acc[mt][nt], afr[mt], bfr[nt]);
        }
        __syncthreads();
    }

    // epilogue: g_s padded [288][288], no guards
#pragma unroll
    for (int mt = 0; mt < 3; mt++) {
#pragma unroll
        for (int half = 0; half < 2; half++) {
            int og = o0 + wm * 48 + mt * 16 + lq + half * 8;
            float* op = g_s + ((size_t)b * 288 + og) * 288 + cc0 + wn * 24 + lr * 2;
#pragma unroll
            for (int nt = 0; nt < 3; nt++) {
                float2 v = make_float2(acc[mt][nt][half * 2],
                                       acc[mt][nt][half * 2 + 1]);
                *(float2*)(op + nt * 8) = v;
            }
        }
    }
}

// ---------------------------------------------------------------------------
// Kernel 2b: softmax over c per (b,o) row -> g_w fp16 (zero-padded).
// One warp per row; grid (36 o-groups, 32 b).
// ---------------------------------------------------------------------------
__global__ void __launch_bounds__(256) softmax_kernel(
        const unsigned char* __restrict__ mask) {
    int b = blockIdx.y;
    int og = blockIdx.x * 8 + (threadIdx.x >> 5);   // 0..287
    int lane = threadIdx.x & 31;
    const float* srow = g_s + ((size_t)b * 288 + og) * 288;
    __half* wout = g_w + ((size_t)b * 288 + og) * 288;
    const unsigned char* mrow = mask + (size_t)b * C_;
    bool dead = (og >= O_);

    float v[9];
    float mx = -CUDART_INF_F;
#pragma unroll
    for (int i = 0; i < 9; i++) {
        int c = lane + 32 * i;
        v[i] = (c < C_ && !mrow[c]) ? srow[c] : -CUDART_INF_F;
        mx = fmaxf(mx, v[i]);
    }
#pragma unroll
    for (int off = 16; off; off >>= 1)
        mx = fmaxf(mx, __shfl_xor_sync(0xffffffffu, mx, off));
    float sum = 0.f;
#pragma unroll
    for (int i = 0; i < 9; i++) {
        v[i] = __expf(v[i] - mx);
        sum += v[i];
    }
#pragma unroll
    for (int off = 16; off; off >>= 1)
        sum += __shfl_xor_sync(0xffffffffu, sum, off);
    float inv = 1.f / sum;
#pragma unroll
    for (int i = 0; i < 9; i++) {
        int c = lane + 32 * i;
        float h = (!dead && c < C_) ? v[i] * inv : 0.f;
        wout[c] = __float2half_rn(h);
    }
}

// ---------------------------------------------------------------------------
// Kernel 3: fp16 mma.sync merge GEMM, meg-resident smem.
// One CTA per (b, t0=128): holds full meg slice [288c x 128t] fp16 in smem
// (loaded once), then 3 o-tiles x 9 k-chunks of MMA against it.
// W [96 x 32] fp16 via cp.async, 3-stage, prefetch distance 2.
// ---------------------------------------------------------------------------
#define MSTR 136                         // halves; 272B rows -> ldsm.t conflict-free
#define WSTR 40                          // halves; 80B rows  -> ldsm   conflict-free
#define WSTG (96 * WSTR * 2)             // 7680 B per W stage
#define MERGE_SMEM (3 * WSTG + 288 * MSTR * 2)   // 23040 + 78336 = 101376

__global__ void __launch_bounds__(256, 2) merge_mma(
        const float* __restrict__ meg,
        float* __restrict__ out) {
    extern __shared__ __half smh[];
    __half* sW = smh;                        // [3][96][WSTR]
    __half* sMeg = smh + 3 * 96 * WSTR;      // [288][MSTR]
    uint32_t sWb = smem_u32(sW), sMb = smem_u32(sMeg);

    int tid = threadIdx.x;
    int wid = tid >> 5, lane = tid & 31;
    int wm = wid >> 2, wn = wid & 3;
    int lq = lane >> 2, lr = lane & 3;
    int t0 = blockIdx.x * 128;
    int b = blockIdx.y;

    const float* megb = meg + (size_t)b * C_ * T_;
    const __half* wbg = g_w + (size_t)b * 288 * 288;

    uint32_t a_row = (uint32_t)(wm * 48 + (lane & 15));
    uint32_t a_ksel = (uint32_t)((lane >> 4) * 8);
    uint32_t b_row = (uint32_t)(lane & 15);
    uint32_t b_nsel = (uint32_t)(wn * 32 + (lane >> 4) * 8);

    auto loadW = [&](int q) {
        if (q < 27 && tid < 128) {
            int ot = q / 9, ch = q - ot * 9;
            const __half* wb = wbg + (size_t)(ot * 96) * 288 + ch * 32;
            uint32_t wdst = sWb + (uint32_t)(q % 3) * WSTG;
#pragma unroll
            for (int it = 0; it < 3; it++) {
                int idx = tid + it * 128;       // 0..383
                int row = idx >> 2, qq = idx & 3;
                CP16(wdst + (uint32_t)(row * (WSTR * 2) + qq * 16),
                     wb + (size_t)row * 288 + qq * 8);
            }
        }
        CP_COMMIT();
    };

    // W prologue (overlaps phase-1 meg load)
    loadW(0);
    loadW(1);

    // Phase 1: meg [273 x 128] fp32 -> sMeg fp16 (rows 273..287 zeroed)
    for (int idx = tid; idx < 288 * 32; idx += 256) {
        int row = idx >> 5, col = (idx & 31) << 2;
        float4 v = make_float4(0.f, 0.f, 0.f, 0.f);
        if (row < C_)
            v = *(const float4*)(megb + (size_t)row * T_ + t0 + col);
        __half2 h01 = __floats2half2_rn(v.x, v.y);
        __half2 h23 = __floats2half2_rn(v.z, v.w);
        uint2 u;
        u.x = *(uint32_t*)&h01;
        u.y = *(uint32_t*)&h23;
        *(uint2*)(sMeg + row * MSTR + col) = u;
    }

    float acc[3][4][4];
#pragma unroll
    for (int i = 0; i < 3; i++)
#pragma unroll
        for (int j = 0; j < 4; j++)
#pragma unroll
            for (int r = 0; r < 4; r++) acc[i][j][r] = 0.f;

    for (int q = 0; q < 27; q++) {
        CP_WAIT(1);
        __syncthreads();          // first iter also publishes sMeg

        uint32_t wbase = sWb + (uint32_t)(q % 3) * WSTG;
        int kc = (q % 9) * 32;

#pragma unroll
        for (int ks = 0; ks < 2; ks++) {
            uint32_t afr[3][4];
#pragma unroll
            for (int mt = 0; mt < 3; mt++)
                LDSM4(afr[mt], wbase + (a_row + mt * 16) * (WSTR * 2)
                               + (ks * 16 + a_ksel) * 2);
            uint32_t bfr[2][4];
#pragma unroll
            for (int ldm = 0; ldm < 2; ldm++)
                LDSM4T(bfr[ldm], sMb + (uint32_t)(kc + ks * 16 + b_row) * (MSTR * 2)
                                 + (b_nsel + ldm * 16) * 2);
#pragma unroll
            for (int mt = 0; mt < 3; mt++)
#pragma unroll
                for (int nt = 0; nt < 4; nt++)
                    MMA_F16(acc[mt][nt], afr[mt], &bfr[nt >> 1][(nt & 1) * 2]);
        }

        loadW(q + 2);             // distance-2 prefetch into stage (q+2)%3

        if ((q % 9) == 8) {       // end of o-tile: write out, reset acc
            int o0 = (q / 9) * 96;
#pragma unroll
            for (int mt = 0; mt < 3; mt++) {
#pragma unroll
                for (int half = 0; half < 2; half++) {
                    int og = o0 + wm * 48 + mt * 16 + lq + half * 8;
                    if (og < O_) {
                        float* op = out + ((size_t)b * O_ + og) * T_
                                    + t0 + wn * 32 + lr * 2;
#pragma unroll
                        for (int nt = 0; nt < 4; nt++) {
                            float2 v = make_float2(acc[mt][nt][half * 2],
                                                   acc[mt][nt][half * 2 + 1]);
                            *(float2*)(op + nt * 8) = v;
                        }
                    }
                }
            }
#pragma unroll
            for (int i = 0; i < 3; i++)
#pragma unroll
                for (int j = 0; j < 4; j++)
#pragma unroll
                    for (int r = 0; r < 4; r++) acc[i][j][r] = 0.f;
        }
    }
}

// ---------------------------------------------------------------------------
extern "C" void kernel_launch(void* const* d_in, const int* in_sizes, int n_in,
                              void* d_out, int out_size) {
    const float* meg = (const float*)d_in[0];
    const float* pos = (const float*)d_in[1];
    const float* heads = (const float*)d_in[2];
    const unsigned char* mask = (const unsigned char*)d_in[3];
    float* out = (float*)d_out;

    int smemS = 4 * 96 * SSTR * 4;   // 55296
    cudaFuncSetAttribute(scores_gemm,
                         cudaFuncAttributeMaxDynamicSharedMemorySize, smemS);
    cudaFuncSetAttribute(merge_mma,
                         cudaFuncAttributeMaxDynamicSharedMemorySize, MERGE_SMEM);

    emb_kernel<<<(B_ * C_ * 144) / 256, 256>>>(pos);
    scores_gemm<<<dim3(3, 3, B_), 256, smemS>>>(heads);
    softmax_kernel<<<dim3(36, B_), 256>>>(mask);
    merge_mma<<<dim3(T_ / 128, B_), 256, MERGE_SMEM>>>(meg, out);
}